// round 16
// baseline (speedup 1.0000x reference)
#include <cuda_runtime.h>
#include <cuda_bf16.h>
#include <stdint.h>

#define E_TOTAL   524288
#define N_AG      16384
#define NTILES    (E_TOTAL / 128)
#define AGG_STRIDE 66

#if defined(__CUDA_ARCH_FEAT_SM103_ALL) || defined(__CUDA_ARCH_FEAT_SM100_ALL) || \
    (defined(__CUDA_ARCH_SPECIFIC__) && (__CUDA_ARCH_SPECIFIC__ >= 1000))
#define HAS_TCGEN05 1
#else
#define HAS_TCGEN05 0
#endif

// ---------------- device scratch ----------------
__device__ float g_agg[N_AG * AGG_STRIDE];
__device__ uint4 g_W2S_hi[8192];   // Wp2: 4 chunks x 32KB (SW128 smem image)
__device__ uint4 g_W2S_lo[8192];
__device__ uint4 g_W3S_hi[2048];   // Wp3: 4 chunks x 8KB
__device__ uint4 g_W3S_lo[2048];
__device__ uint4 g_WR1S_hi[2048];
__device__ uint4 g_WR1S_lo[2048];
__device__ uint4 g_WR2S_hi[8192];
__device__ uint4 g_WR2S_lo[8192];

// ---------------- helpers ----------------
__device__ __forceinline__ uint32_t smem_u32(const void* p) {
    uint32_t a;
    asm("{ .reg .u64 t; cvta.to.shared.u64 t, %1; cvt.u32.u64 %0, t; }" : "=r"(a) : "l"(p));
    return a;
}
__device__ __forceinline__ uint32_t swz128(uint32_t off) { return off ^ ((off >> 3) & 0x70); }

__device__ __forceinline__ void split2(float v0, float v1, uint32_t& hi, uint32_t& lo) {
    const uint32_t u0 = __float_as_uint(v0), u1 = __float_as_uint(v1);
    hi = __byte_perm(u0, u1, 0x7632);
    const float l0 = v0 - __uint_as_float(u0 & 0xFFFF0000u);
    const float l1 = v1 - __uint_as_float(u1 & 0xFFFF0000u);
    lo = __byte_perm(__float_as_uint(l0), __float_as_uint(l1), 0x7632);
}

#if HAS_TCGEN05
__device__ __forceinline__ uint64_t mk_desc(uint32_t addr) {
    const uint64_t base = (uint64_t(2) << 61) | (uint64_t(1) << 46) | (uint64_t(64) << 32) | (uint64_t(1) << 16);
    return base | ((uint64_t)(addr >> 4) & 0x3FFF);
}
__device__ __forceinline__ void mma_f16_ss(uint32_t d, uint64_t a, uint64_t b, uint32_t idesc, uint32_t en) {
    asm volatile(
        "{\n\t.reg .pred p;\n\tsetp.ne.u32 p, %5, 0;\n\t"
        "tcgen05.mma.cta_group::1.kind::f16 [%0], %1, %2, %3, {%4,%4,%4,%4}, p;\n\t}"
        :: "r"(d), "l"(a), "l"(b), "r"(idesc), "r"(0u), "r"(en) : "memory");
}
#define TC_ALLOC(sa, n)   asm volatile("tcgen05.alloc.cta_group::1.sync.aligned.shared::cta.b32 [%0], %1;" :: "r"(sa), "r"(n) : "memory")
#define TC_RELINQ()       asm volatile("tcgen05.relinquish_alloc_permit.cta_group::1.sync.aligned;")
#define TC_DEALLOC(t, n)  asm volatile("tcgen05.dealloc.cta_group::1.sync.aligned.b32 %0, %1;" :: "r"(t), "r"(n))
#define TC_COMMIT(mb)     asm volatile("tcgen05.commit.cta_group::1.mbarrier::arrive::one.shared::cluster.b64 [%0];" :: "r"(mb) : "memory")
#define TC_FENCE_AFTER()  asm volatile("tcgen05.fence::after_thread_sync;" ::: "memory")
#define TC_FENCE_BEFORE() asm volatile("tcgen05.fence::before_thread_sync;" ::: "memory")
#define TC_WAIT_LD()      asm volatile("tcgen05.wait::ld.sync.aligned;" ::: "memory")
#define FENCE_ASYNC()     asm volatile("fence.proxy.async.shared::cta;" ::: "memory")
#define MBAR_INIT(mb, c)  asm volatile("mbarrier.init.shared.b64 [%0], %1;" :: "r"(mb), "r"(c) : "memory")
#define MBAR_EXPECT_TX(mb, n) asm volatile("mbarrier.arrive.expect_tx.shared.b64 _, [%0], %1;" :: "r"(mb), "r"(n) : "memory")
#define BULK_CP(dst, src, bytes, mbar) \
    asm volatile("cp.async.bulk.shared::cta.global.mbarrier::complete_tx::bytes [%0], [%1], %2, [%3];" \
        :: "r"(dst), "l"(src), "r"(bytes), "r"(mbar) : "memory")

#define MBAR_WAIT(mb, par) do { \
    uint32_t _m = (mb); uint32_t _p = (par); uint32_t _d; \
    asm volatile("{\n\t.reg .pred p;\n\t" \
        "mbarrier.try_wait.parity.acquire.cta.shared::cta.b64 p, [%1], %2;\n\t" \
        "selp.b32 %0, 1, 0, p;\n\t}" : "=r"(_d) : "r"(_m), "r"(_p) : "memory"); \
    if (!_d) { \
        asm volatile("{\n\t.reg .pred P1;\n\t" \
            "WL_%=:\n\t" \
            "mbarrier.try_wait.parity.acquire.cta.shared::cta.b64 P1, [%0], %1, 0x989680;\n\t" \
            "@P1 bra.uni WD_%=;\n\t" \
            "bra.uni WL_%=;\n\t" \
            "WD_%=:\n\t}" :: "r"(_m), "r"(_p) : "memory"); \
    } \
} while (0)

#define TC_LD_X32(r, ta) \
    asm volatile("tcgen05.ld.sync.aligned.32x32b.x32.b32 " \
        "{%0,%1,%2,%3,%4,%5,%6,%7,%8,%9,%10,%11,%12,%13,%14,%15," \
        "%16,%17,%18,%19,%20,%21,%22,%23,%24,%25,%26,%27,%28,%29,%30,%31}, [%32];" \
        : "=r"((r)[0]),"=r"((r)[1]),"=r"((r)[2]),"=r"((r)[3]),"=r"((r)[4]),"=r"((r)[5]),"=r"((r)[6]),"=r"((r)[7]), \
          "=r"((r)[8]),"=r"((r)[9]),"=r"((r)[10]),"=r"((r)[11]),"=r"((r)[12]),"=r"((r)[13]),"=r"((r)[14]),"=r"((r)[15]), \
          "=r"((r)[16]),"=r"((r)[17]),"=r"((r)[18]),"=r"((r)[19]),"=r"((r)[20]),"=r"((r)[21]),"=r"((r)[22]),"=r"((r)[23]), \
          "=r"((r)[24]),"=r"((r)[25]),"=r"((r)[26]),"=r"((r)[27]),"=r"((r)[28]),"=r"((r)[29]),"=r"((r)[30]),"=r"((r)[31]) \
        : "r"(ta))
#endif // HAS_TCGEN05

// idescs: dtype=F32, a/b=BF16, M=128; N=256 / 128 / 64
#define IDESC_N256 0x8400490u
#define IDESC_N128 0x8200490u
#define IDESC_N64  0x8100490u

// ---------------- edge smem layout (106KB -> 2 CTAs/SM) ----------------
#define E_TMEM  0
#define E_MBA   16      // commit-A (after Bh-reading MMAs)
#define E_MBB   24      // commit-B (after all MMAs of the round)
#define E_MBT   32      // B-hi DMA barrier
#define E_MBTL  48      // B-lo DMA barrier
#define E_SSEG  64      // 2 x 128 ints
#define E_BP2   1088
#define E_BP3   2112
#define E_BP1   2368
#define E_WP1   3392    // 1024 f -> ends 7488
#define E_H3X   7488    // h3 cols 63..65: 3 x 128 f = 1536B -> ends 9024
#define E_A     9216    // 32KB: hi 16K + lo 16K (h3 cols 0..62 alias here, stride 129)
#define E_B     43008   // 64KB: hi 32K + lo 32K
#define EDGE_SMEM 108544

// ---------------- agent smem layout (R9, unchanged) ----------------
#define AG_TMEM  0
#define AG_MBAR0 16
#define AG_MBAR1 24
#define AG_MBT0  32
#define AG_MBT1  40
#define AG_BP2   1088
#define AG_BP1   2368
#define AG_WP1   3392
#define AG_A0    8192
#define AG_A1    40960
#define AG_B0    73728
#define AG_B1    139264
#define AGENT_SMEM 204800

#define NT_EDGE 256
#define NCTA_EDGE 296

// ---------------- merged weight prep + agg zero ----------------
__global__ void prep_kernel(const float* __restrict__ Wp2, const float* __restrict__ Wp3,
                            const float* __restrict__ Wr1, const float* __restrict__ Wr2) {
    int i = blockIdx.x * blockDim.x + threadIdx.x;
    if (i < N_AG * AGG_STRIDE) g_agg[i] = 0.0f;
    if (i < 256 * 256) {
        int n = i >> 8, k = i & 255;
        {
            float w = Wp2[k * 256 + n];
            __nv_bfloat16 h = __float2bfloat16(w);
            float r = w - __bfloat162float(h);
            const uint32_t off = (k >> 6) * 32768 + swz128(n * 128 + (k & 63) * 2);
            *(__nv_bfloat16*)((char*)g_W2S_hi + off) = h;
            *(__nv_bfloat16*)((char*)g_W2S_lo + off) = __float2bfloat16(r);
        }
        {
            float w = Wr2[k * 256 + n];
            __nv_bfloat16 h = __float2bfloat16(w);
            float r = w - __bfloat162float(h);
            const uint32_t off = (k >> 6) * 32768 + swz128(n * 128 + (k & 63) * 2);
            *(__nv_bfloat16*)((char*)g_WR2S_hi + off) = h;
            *(__nv_bfloat16*)((char*)g_WR2S_lo + off) = __float2bfloat16(r);
        }
    }
    if (i < 64 * 256) {
        int n = i >> 8, k = i & 255;
        float w = Wp3[k * 64 + n];
        __nv_bfloat16 h = __float2bfloat16(w);
        float r = w - __bfloat162float(h);
        const uint32_t off = (k >> 6) * 8192 + swz128(n * 128 + (k & 63) * 2);
        *(__nv_bfloat16*)((char*)g_W3S_hi + off) = h;
        *(__nv_bfloat16*)((char*)g_W3S_lo + off) = __float2bfloat16(r);
    }
    if (i < 256 * 64) {
        int n = i >> 6, k = i & 63;
        float w = Wr1[k * 256 + n];
        __nv_bfloat16 h = __float2bfloat16(w);
        float r = w - __bfloat162float(h);
        const uint32_t off = swz128(n * 128 + k * 2);
        *(__nv_bfloat16*)((char*)g_WR1S_hi + off) = h;
        *(__nv_bfloat16*)((char*)g_WR1S_lo + off) = __float2bfloat16(r);
    }
}

// barrier term + segmented-scan epilogue.
// h3 cols 0..62 live at h3A stride 129; cols 63..65 at h3X stride 128.
__device__ __forceinline__ void do_epilogue(float* h3A, float* h3X, const int* ss,
                                            float px, float py, int tid) {
    if (tid < 128) {
        const float d = sqrtf(px * px + py * py);
        const float s = -1.0f / (d * (d - 0.18f));
        h3X[128 + tid] = px * s;   // col 64
        h3X[256 + tid] = py * s;   // col 65
    }
    __syncthreads();
    const int sc = (tid < 66) ? 0 : ((tid >= 128 && tid < 194) ? 1 : -1);
    if (sc >= 0) {
        const int col = (sc == 0) ? tid : (tid - 128);
        const int eb = sc * 64;
        const float* colp = (col < 63) ? (h3A + col * 129 + eb)
                                       : (h3X + (col - 63) * 128 + eb);
        int cur = ss[eb];
        float run = 0.0f;
        #pragma unroll 4
        for (int e = 0; e < 64; e++) {
            const int sg = ss[eb + e];
            if (sg != cur) { atomicAdd(&g_agg[cur * 66 + col], run); run = 0.0f; cur = sg; }
            run += colp[e];
        }
        atomicAdd(&g_agg[cur * 66 + col], run);
    }
    __syncthreads();
}

// store one D3 half (32 cols) into split h3 staging
__device__ __forceinline__ void store_h3(const uint32_t* r0, const float* bp3s,
                                         float* h3A, float* h3X, int half, int edge) {
    #pragma unroll
    for (int c = 0; c < 32; c++) {
        const int col = half * 32 + c;
        const float v = __uint_as_float(r0[c]) + bp3s[col];
        if (col < 63) h3A[col * 129 + edge] = v;
        else          h3X[(col - 63) * 128 + edge] = v;
    }
}

// ---------------- edge kernel: R14 + de-aliased h3 staging + tile-start DMA ----------------
__global__ void __launch_bounds__(NT_EDGE, 2) edge_kernel(
    const float* __restrict__ ef, const int* __restrict__ seg,
    const float* __restrict__ Wp1, const float* __restrict__ bp1,
    const float* __restrict__ bp2, const float* __restrict__ bp3,
    const float* __restrict__ Wp2g, const float* __restrict__ Wp3g)
{
    extern __shared__ char sm[];
    const uint32_t smb = smem_u32(sm);
    const int tid = threadIdx.x;
    const int wid = tid >> 5;
    const int edge = tid & 127;
    const int half = tid >> 7;

    int*   sbuf = (int*)(sm + E_SSEG);
    float* bp2s = (float*)(sm + E_BP2);
    float* bp3s = (float*)(sm + E_BP3);
    float* bp1s = (float*)(sm + E_BP1);
    float* wp1s = (float*)(sm + E_WP1);
    float* h3A  = (float*)(sm + E_A);       // cols 0..62 (A buffer, dead at tile start)
    float* h3X  = (float*)(sm + E_H3X);     // cols 63..65

#if HAS_TCGEN05
    if (wid == 0) { TC_ALLOC(smb + E_TMEM, 256); TC_RELINQ(); }
    if (tid == 0) {
        MBAR_INIT(smb + E_MBA, 1);
        MBAR_INIT(smb + E_MBB, 1);
        MBAR_INIT(smb + E_MBT, 1);
        MBAR_INIT(smb + E_MBTL, 1);
    }
#endif

    wp1s[tid] = Wp1[tid];             wp1s[tid + 256] = Wp1[tid + 256];
    wp1s[tid + 512] = Wp1[tid + 512]; wp1s[tid + 768] = Wp1[tid + 768];
    bp1s[tid] = bp1[tid];
    bp2s[tid] = bp2[tid];
    if (tid < 64) bp3s[tid] = bp3[tid];
    __syncthreads();

#if HAS_TCGEN05
    uint32_t tmem;
    asm volatile("ld.shared.b32 %0, [%1];" : "=r"(tmem) : "r"(smb + E_TMEM));
    const uint32_t tD2 = tmem;        // 256 cols
    const uint32_t tD3 = tmem;        // cols 0-63, read before clobber
    const uint32_t warp_off = (uint32_t)(wid & 3) << 21;
    int parA = 0, parB = 0, pend = 0;
    int pt = 0, ptl = 0;

    const char* w2h = (const char*)g_W2S_hi;
    const char* w2l = (const char*)g_W2S_lo;
    const char* w3h = (const char*)g_W3S_hi;
    const char* w3l = (const char*)g_W3S_lo;

    float4 xcur = make_float4(0.f, 0.f, 0.f, 0.f), xprev;
    int cnt = 0;

    for (int tile = blockIdx.x; tile < NTILES; tile += gridDim.x, cnt++) {
        const int e0 = tile * 128;
        const int sb = cnt & 1;
        xprev = xcur;
        xcur = ((const float4*)ef)[e0 + edge];
        if (tid < 128) sbuf[sb * 128 + tid] = seg[e0 + tid];

        // drain previous tile (both commits) — frees A + B + D3 ready
        if (pend) {
            MBAR_WAIT(smb + E_MBA, parA); parA ^= 1;
            MBAR_WAIT(smb + E_MBB, parB); parB ^= 1;
            pend = 0;
        }
        TC_FENCE_AFTER();

        // kick chunk-0 W2 DMA NOW — hidden behind the epilogue
        if (tid == 0) {
            MBAR_EXPECT_TX(smb + E_MBT, 32768);
            BULK_CP(smb + E_B, w2h, 32768, smb + E_MBT);
            MBAR_EXPECT_TX(smb + E_MBTL, 32768);
            BULK_CP(smb + E_B + 32768, w2l, 32768, smb + E_MBTL);
        }

        // -------- epilogue of PREVIOUS tile --------
        if (cnt > 0) {
            uint32_t r0[32];
            TC_LD_X32(r0, tD3 + half * 32 + warp_off);
            TC_WAIT_LD();
            TC_FENCE_BEFORE();
            store_h3(r0, bp3s, h3A, h3X, half, edge);
            do_epilogue(h3A, h3X, sbuf + (sb ^ 1) * 128, xprev.x, xprev.y, tid);
        }

        // ================= layer 2: K=256 in 4 chunks of 64 =================
        for (int kc = 0; kc < 4; kc++) {
            if (kc > 0) {
                // commit-A of kc-1: Bh free -> early Bh DMA
                MBAR_WAIT(smb + E_MBA, parA); parA ^= 1;
                if (tid == 0) {
                    MBAR_EXPECT_TX(smb + E_MBT, 32768);
                    BULK_CP(smb + E_B, w2h + kc * 32768, 32768, smb + E_MBT);
                }
                // commit-B of kc-1: Bl + A free
                MBAR_WAIT(smb + E_MBB, parB); parB ^= 1;
                if (tid == 0) {
                    MBAR_EXPECT_TX(smb + E_MBTL, 32768);
                    BULK_CP(smb + E_B + 32768, w2l + kc * 32768, 32768, smb + E_MBTL);
                }
            }
            // kc==0: DMAs already in flight from tile start

            // layer-1 on the fly: this thread does 32 of the 64 chunk cols
            #pragma unroll
            for (int g = 0; g < 4; g++) {
                const int gg = half * 4 + g;
                uint32_t hi4[4], lo4[4];
                #pragma unroll
                for (int q = 0; q < 4; q++) {
                    const int c = kc * 64 + gg * 8 + q * 2;
                    float v0 = fmaf(xcur.x, wp1s[c],       fmaf(xcur.y, wp1s[256 + c],
                               fmaf(xcur.z, wp1s[512 + c], fmaf(xcur.w, wp1s[768 + c], bp1s[c]))));
                    float v1 = fmaf(xcur.x, wp1s[c + 1],       fmaf(xcur.y, wp1s[256 + c + 1],
                               fmaf(xcur.z, wp1s[512 + c + 1], fmaf(xcur.w, wp1s[768 + c + 1], bp1s[c + 1]))));
                    v0 = fmaxf(v0, 0.0f); v1 = fmaxf(v1, 0.0f);
                    split2(v0, v1, hi4[q], lo4[q]);
                }
                const uint32_t so = swz128(edge * 128 + gg * 16);
                *(uint4*)(sm + E_A + so)         = make_uint4(hi4[0], hi4[1], hi4[2], hi4[3]);
                *(uint4*)(sm + E_A + 16384 + so) = make_uint4(lo4[0], lo4[1], lo4[2], lo4[3]);
            }
            FENCE_ASYNC();
            __syncthreads();

            if (tid == 0) {
                const uint64_t dAh = mk_desc(smb + E_A);
                const uint64_t dAl = dAh + 1024;   // +16KB
                const uint64_t dBh = mk_desc(smb + E_B);
                const uint64_t dBl = dBh + 2048;   // +32KB
                MBAR_WAIT(smb + E_MBT, pt); pt ^= 1;
                #pragma unroll
                for (int s = 0; s < 4; s++) {
                    mma_f16_ss(tD2, dAh + s * 2, dBh + s * 2, IDESC_N256, !(kc == 0 && s == 0));
                    mma_f16_ss(tD2, dAl + s * 2, dBh + s * 2, IDESC_N256, 1);
                }
                TC_COMMIT(smb + E_MBA);
                MBAR_WAIT(smb + E_MBTL, ptl); ptl ^= 1;
                #pragma unroll
                for (int s = 0; s < 4; s++)
                    mma_f16_ss(tD2, dAh + s * 2, dBl + s * 2, IDESC_N256, 1);
                TC_COMMIT(smb + E_MBB);
            }
            pend = 1;
        }

        // ================= layer 3: 4 slices, D3 = cols 0-63 =================
        for (int i = 0; i < 4; i++) {
            MBAR_WAIT(smb + E_MBA, parA); parA ^= 1;
            MBAR_WAIT(smb + E_MBB, parB); parB ^= 1;
            pend = 0;
            TC_FENCE_AFTER();

            if (tid == 0) {
                MBAR_EXPECT_TX(smb + E_MBT, 16384);
                BULK_CP(smb + E_B,        w3h + i * 8192, 8192, smb + E_MBT);
                BULK_CP(smb + E_B + 8192, w3l + i * 8192, 8192, smb + E_MBT);
            }

            uint32_t r0[32];
            TC_LD_X32(r0, tD2 + i * 64 + half * 32 + warp_off);
            TC_WAIT_LD();

            #pragma unroll
            for (int g = 0; g < 4; g++) {
                const int gg = half * 4 + g;
                uint32_t hi4[4], lo4[4];
                #pragma unroll
                for (int q = 0; q < 4; q++) {
                    const int j = g * 8 + q * 2;
                    const int c = i * 64 + half * 32 + j;
                    float v0 = fmaxf(__uint_as_float(r0[j])     + bp2s[c],     0.0f);
                    float v1 = fmaxf(__uint_as_float(r0[j + 1]) + bp2s[c + 1], 0.0f);
                    split2(v0, v1, hi4[q], lo4[q]);
                }
                const uint32_t so = swz128(edge * 128 + gg * 16);
                *(uint4*)(sm + E_A + so)         = make_uint4(hi4[0], hi4[1], hi4[2], hi4[3]);
                *(uint4*)(sm + E_A + 16384 + so) = make_uint4(lo4[0], lo4[1], lo4[2], lo4[3]);
            }
            FENCE_ASYNC();
            TC_FENCE_BEFORE();
            __syncthreads();

            if (tid == 0) {
                TC_FENCE_AFTER();
                MBAR_WAIT(smb + E_MBT, pt); pt ^= 1;
                const uint64_t dAh = mk_desc(smb + E_A);
                const uint64_t dAl = dAh + 1024;
                const uint64_t dBh = mk_desc(smb + E_B);
                const uint64_t dBl = dBh + 512;    // +8KB
                #pragma unroll
                for (int s = 0; s < 4; s++) {
                    mma_f16_ss(tD3, dAh + s * 2, dBh + s * 2, IDESC_N64, !(i == 0 && s == 0));
                    mma_f16_ss(tD3, dAl + s * 2, dBh + s * 2, IDESC_N64, 1);
                }
                TC_COMMIT(smb + E_MBA);
                #pragma unroll
                for (int s = 0; s < 4; s++)
                    mma_f16_ss(tD3, dAh + s * 2, dBl + s * 2, IDESC_N64, 1);
                TC_COMMIT(smb + E_MBB);
            }
            pend = 1;
        }
    }

    // -------- final drain + epilogue of the last tile --------
    if (pend) {
        MBAR_WAIT(smb + E_MBA, parA); parA ^= 1;
        MBAR_WAIT(smb + E_MBB, parB); parB ^= 1;
        pend = 0;
    }
    if (cnt > 0) {
        TC_FENCE_AFTER();
        uint32_t r0[32];
        TC_LD_X32(r0, tD3 + half * 32 + warp_off);
        TC_WAIT_LD();
        TC_FENCE_BEFORE();
        store_h3(r0, bp3s, h3A, h3X, half, edge);
        do_epilogue(h3A, h3X, sbuf + ((cnt - 1) & 1) * 128, xcur.x, xcur.y, tid);
    }
    __syncthreads();
    if (wid == 0) TC_DEALLOC(tmem, 256);
#else
    // ---------- correct scalar fallback (non-'a' targets only) ----------
    for (int tile = blockIdx.x; tile < NTILES; tile += gridDim.x) {
        const int e0 = tile * 128;
        const float4 x = ((const float4*)ef)[e0 + edge];
        if (tid < 128) sbuf[tid] = seg[e0 + tid];
        __syncthreads();
        if (tid < 128) {
            float h1v[256];
            for (int k = 0; k < 256; k++) {
                float v = fmaf(x.x, wp1s[k],       fmaf(x.y, wp1s[256 + k],
                          fmaf(x.z, wp1s[512 + k], fmaf(x.w, wp1s[768 + k], bp1s[k]))));
                h1v[k] = fmaxf(v, 0.0f);
            }
            float h3a[64];
            for (int n = 0; n < 64; n++) h3a[n] = bp3s[n];
            for (int j = 0; j < 256; j++) {
                float s = bp2s[j];
                for (int k = 0; k < 256; k++)
                    s = fmaf(h1v[k], Wp2g[k * 256 + j], s);
                s = fmaxf(s, 0.0f);
                for (int n = 0; n < 64; n++)
                    h3a[n] = fmaf(s, Wp3g[j * 64 + n], h3a[n]);
            }
            for (int c = 0; c < 64; c++) {
                if (c < 63) h3A[c * 129 + tid] = h3a[c];
                else        h3X[(c - 63) * 128 + tid] = h3a[c];
            }
        }
        __syncthreads();
        do_epilogue(h3A, h3X, sbuf, x.x, x.y, tid);
        __syncthreads();
    }
#endif
}

// ---------------- agent kernel: tcgen05, 128 agents/CTA, one wave (R9 verbatim) ----------------
__global__ void __launch_bounds__(256, 1) agent_kernel(
    const float* __restrict__ Wr1, const float* __restrict__ br1,
    const float* __restrict__ Wr2, const float* __restrict__ br2,
    const float* __restrict__ Wr3, const float* __restrict__ br3,
    float* __restrict__ out)
{
    extern __shared__ char sm[];
    const uint32_t smb = smem_u32(sm);
    const int tid = threadIdx.x;
    const int wid = tid >> 5;
    const int edge = tid & 127;
    const int half = tid >> 7;
    const int a0 = blockIdx.x * 128;

    float* br1s = (float*)(sm + AG_BP1);
    float* br2s = (float*)(sm + AG_BP2);
    float* w3s  = (float*)(sm + AG_WP1);

    br1s[tid] = br1[tid];
    br2s[tid] = br2[tid];
    w3s[tid] = Wr3[tid];
    w3s[tid + 256] = Wr3[tid + 256];

#if HAS_TCGEN05
    if (wid == 0) { TC_ALLOC(smb + AG_TMEM, 512); TC_RELINQ(); }
    if (tid == 0) {
        MBAR_INIT(smb + AG_MBAR0, 1); MBAR_INIT(smb + AG_MBAR1, 1);
        MBAR_INIT(smb + AG_MBT0, 1);  MBAR_INIT(smb + AG_MBT1, 1);
    }
    __syncthreads();

    uint32_t tmem;
    asm volatile("ld.shared.b32 %0, [%1];" : "=r"(tmem) : "r"(smb + AG_TMEM));
    const uint32_t tD1 = tmem;
    const uint32_t tD2 = tmem + 256;
    const uint32_t warp_off = (uint32_t)(wid & 3) << 21;
    int par0 = 0, par1 = 0, pend0 = 0, pend1 = 0;
    int pt0 = 0, pt1 = 0;

#define WAIT_BUF0() do { if (pend0) { MBAR_WAIT(smb + AG_MBAR0, par0); par0 ^= 1; pend0 = 0; } } while (0)
#define WAIT_BUF1() do { if (pend1) { MBAR_WAIT(smb + AG_MBAR1, par1); par1 ^= 1; pend1 = 0; } } while (0)

    if (tid == 0) {
        MBAR_EXPECT_TX(smb + AG_MBT0, 65536);
        BULK_CP(smb + AG_B0,         (const char*)g_WR1S_hi, 32768, smb + AG_MBT0);
        BULK_CP(smb + AG_B0 + 32768, (const char*)g_WR1S_lo, 32768, smb + AG_MBT0);
    }
    {
        char* A = sm + AG_A0;
        const float* aggrow = g_agg + (size_t)(a0 + edge) * 66 + half * 32;
        #pragma unroll
        for (int g = 0; g < 4; g++) {
            const int gg = half * 4 + g;
            uint32_t hi4[4], lo4[4];
            #pragma unroll
            for (int q = 0; q < 4; q++) {
                const int j = g * 8 + q * 2;
                const float2 v = *(const float2*)&aggrow[j];
                split2(v.x, v.y, hi4[q], lo4[q]);
            }
            const uint32_t so = swz128(edge * 128 + gg * 16);
            *(uint4*)(A + so)         = make_uint4(hi4[0], hi4[1], hi4[2], hi4[3]);
            *(uint4*)(A + 16384 + so) = make_uint4(lo4[0], lo4[1], lo4[2], lo4[3]);
        }
    }
    FENCE_ASYNC();
    __syncthreads();

    if (tid == 0) {
        MBAR_WAIT(smb + AG_MBT0, pt0); pt0 ^= 1;
        const uint64_t dAh = mk_desc(smb + AG_A0);
        const uint64_t dAl = dAh + 1024;
        const uint64_t dBh = mk_desc(smb + AG_B0);
        const uint64_t dBl = dBh + 2048;
        #pragma unroll
        for (int s = 0; s < 4; s++) {
            #pragma unroll
            for (int h = 0; h < 2; h++) {
                const uint32_t d = tD1 + h * 128;
                const uint64_t bo = (uint64_t)h * 1024 + s * 2;
                mma_f16_ss(d, dAh + s * 2, dBh + bo, IDESC_N128, !(s == 0));
                mma_f16_ss(d, dAh + s * 2, dBl + bo, IDESC_N128, 1);
                mma_f16_ss(d, dAl + s * 2, dBh + bo, IDESC_N128, 1);
            }
        }
        TC_COMMIT(smb + AG_MBAR0);
    }
    pend0 = 1;
    WAIT_BUF0();
    TC_FENCE_AFTER();

    for (int kc = 0; kc < 4; kc++) {
        const int buf = (kc & 1) ^ 1;
        if (buf) WAIT_BUF1(); else WAIT_BUF0();

        char* A = sm + (buf ? AG_A1 : AG_A0);
        const uint32_t Bsm = smb + (buf ? AG_B1 : AG_B0);
        const uint32_t mbt = smb + (buf ? AG_MBT1 : AG_MBT0);

        if (tid == 0) {
            MBAR_EXPECT_TX(mbt, 65536);
            BULK_CP(Bsm,         (const char*)g_WR2S_hi + kc * 32768, 32768, mbt);
            BULK_CP(Bsm + 32768, (const char*)g_WR2S_lo + kc * 32768, 32768, mbt);
        }

        uint32_t r0[32];
        TC_LD_X32(r0, tD1 + kc * 64 + half * 32 + warp_off);
        TC_WAIT_LD();

        #pragma unroll
        for (int g = 0; g < 4; g++) {
            const int gg = half * 4 + g;
            uint32_t hi4[4], lo4[4];
            #pragma unroll
            for (int q = 0; q < 4; q++) {
                const int j = g * 8 + q * 2;
                const int c = kc * 64 + half * 32 + j;
                float v0 = fmaxf(__uint_as_float(r0[j])     + br1s[c],     0.0f);
                float v1 = fmaxf(__uint_as_float(r0[j + 1]) + br1s[c + 1], 0.0f);
                split2(v0, v1, hi4[q], lo4[q]);
            }
            const uint32_t so = swz128(edge * 128 + gg * 16);
            *(uint4*)(A + so)         = make_uint4(hi4[0], hi4[1], hi4[2], hi4[3]);
            *(uint4*)(A + 16384 + so) = make_uint4(lo4[0], lo4[1], lo4[2], lo4[3]);
        }
        FENCE_ASYNC();
        TC_FENCE_BEFORE();
        __syncthreads();

        if (tid == 0) {
            TC_FENCE_AFTER();
            if (buf) { MBAR_WAIT(mbt, pt1); pt1 ^= 1; }
            else     { MBAR_WAIT(mbt, pt0); pt0 ^= 1; }
            const uint64_t dAh = mk_desc(smb + (uint32_t)(A - sm));
            const uint64_t dAl = dAh + 1024;
            const uint64_t dBh = mk_desc(Bsm);
            const uint64_t dBl = dBh + 2048;
            #pragma unroll
            for (int s = 0; s < 4; s++) {
                #pragma unroll
                for (int h = 0; h < 2; h++) {
                    const uint32_t d = tD2 + h * 128;
                    const uint64_t bo = (uint64_t)h * 1024 + s * 2;
                    mma_f16_ss(d, dAh + s * 2, dBh + bo, IDESC_N128, !(kc == 0 && s == 0));
                    mma_f16_ss(d, dAh + s * 2, dBl + bo, IDESC_N128, 1);
                    mma_f16_ss(d, dAl + s * 2, dBh + bo, IDESC_N128, 1);
                }
            }
            TC_COMMIT(smb + (buf ? AG_MBAR1 : AG_MBAR0));
        }
        if (buf) pend1 = 1; else pend0 = 1;
    }

    WAIT_BUF0();
    WAIT_BUF1();
    TC_FENCE_AFTER();

    if (tid < 128) {
        float s0 = br3[0] + g_agg[(size_t)(a0 + edge) * 66 + 64];
        float s1 = br3[1] + g_agg[(size_t)(a0 + edge) * 66 + 65];
        #pragma unroll
        for (int b = 0; b < 8; b++) {
            uint32_t r0[32];
            TC_LD_X32(r0, tD2 + b * 32 + warp_off);
            TC_WAIT_LD();
            #pragma unroll
            for (int j = 0; j < 32; j++) {
                const int c = b * 32 + j;
                const float v = fmaxf(__uint_as_float(r0[j]) + br2s[c], 0.0f);
                s0 = fmaf(v, w3s[c * 2],     s0);
                s1 = fmaf(v, w3s[c * 2 + 1], s1);
            }
        }
        TC_FENCE_BEFORE();
        out[(a0 + edge) * 2]     = s0;
        out[(a0 + edge) * 2 + 1] = s1;
    }
    __syncthreads();
    if (wid == 0) TC_DEALLOC(tmem, 512);
#undef WAIT_BUF0
#undef WAIT_BUF1
#else
    __syncthreads();
    if (tid < 128) {
        const int a = a0 + edge;
        float r1v[256];
        for (int n = 0; n < 256; n++) {
            float s = br1s[n];
            for (int k = 0; k < 64; k++)
                s = fmaf(g_agg[(size_t)a * 66 + k], Wr1[k * 256 + n], s);
            r1v[n] = fmaxf(s, 0.0f);
        }
        float s0 = br3[0] + g_agg[(size_t)a * 66 + 64];
        float s1 = br3[1] + g_agg[(size_t)a * 66 + 65];
        for (int n = 0; n < 256; n++) {
            float s = br2s[n];
            for (int k = 0; k < 256; k++)
                s = fmaf(r1v[k], Wr2[k * 256 + n], s);
            s = fmaxf(s, 0.0f);
            s0 = fmaf(s, w3s[n * 2],     s0);
            s1 = fmaf(s, w3s[n * 2 + 1], s1);
        }
        out[a * 2]     = s0;
        out[a * 2 + 1] = s1;
    }
#endif
}

// ---------------- launch ----------------
extern "C" void kernel_launch(void* const* d_in, const int* in_sizes, int n_in,
                              void* d_out, int out_size) {
    const float* ef  = (const float*)d_in[0];
    const int*   seg = (const int*)  d_in[1];
    const float* Wp1 = (const float*)d_in[2];
    const float* bp1 = (const float*)d_in[3];
    const float* Wp2 = (const float*)d_in[4];
    const float* bp2 = (const float*)d_in[5];
    const float* Wp3 = (const float*)d_in[6];
    const float* bp3 = (const float*)d_in[7];
    const float* Wr1 = (const float*)d_in[8];
    const float* br1 = (const float*)d_in[9];
    const float* Wr2 = (const float*)d_in[10];
    const float* br2 = (const float*)d_in[11];
    const float* Wr3 = (const float*)d_in[12];
    const float* br3 = (const float*)d_in[13];
    float* out = (float*)d_out;

    cudaFuncSetAttribute(edge_kernel,  cudaFuncAttributeMaxDynamicSharedMemorySize, EDGE_SMEM);
    cudaFuncSetAttribute(agent_kernel, cudaFuncAttributeMaxDynamicSharedMemorySize, AGENT_SMEM);

    prep_kernel<<<(N_AG * AGG_STRIDE + 255) / 256, 256>>>(Wp2, Wp3, Wr1, Wr2);
    edge_kernel<<<NCTA_EDGE, NT_EDGE, EDGE_SMEM>>>(ef, seg, Wp1, bp1, bp2, bp3, Wp2, Wp3);
    agent_kernel<<<N_AG / 128, 256, AGENT_SMEM>>>(Wr1, br1, Wr2, br2, Wr3, br3, out);
}

// round 17
// speedup vs baseline: 1.2411x; 1.2411x over previous
#include <cuda_runtime.h>
#include <cuda_bf16.h>
#include <cuda_fp16.h>
#include <stdint.h>

#define E_TOTAL   524288
#define N_AG      16384
#define NTILES    (E_TOTAL / 128)
#define AGG_STRIDE 66

#if defined(__CUDA_ARCH_FEAT_SM103_ALL) || defined(__CUDA_ARCH_FEAT_SM100_ALL) || \
    (defined(__CUDA_ARCH_SPECIFIC__) && (__CUDA_ARCH_SPECIFIC__ >= 1000))
#define HAS_TCGEN05 1
#else
#define HAS_TCGEN05 0
#endif

// ---------------- device scratch ----------------
__device__ float g_agg[N_AG * AGG_STRIDE];
// Edge weights: fp16 SW128 images, per-K64-chunk blocks.
__device__ uint4 g_W2S_hi[8192];   // Wp2: 4 chunks x 32KB
__device__ uint4 g_W2S_lo[8192];
__device__ uint4 g_W3S_hi[2048];   // Wp3: 4 chunks x 8KB
__device__ uint4 g_W3S_lo[2048];
// Agent weights: bf16 SW128 images (unchanged)
__device__ uint4 g_WR1S_hi[2048];
__device__ uint4 g_WR1S_lo[2048];
__device__ uint4 g_WR2S_hi[8192];
__device__ uint4 g_WR2S_lo[8192];

// ---------------- helpers ----------------
__device__ __forceinline__ uint32_t smem_u32(const void* p) {
    uint32_t a;
    asm("{ .reg .u64 t; cvta.to.shared.u64 t, %1; cvt.u32.u64 %0, t; }" : "=r"(a) : "l"(p));
    return a;
}
__device__ __forceinline__ uint32_t swz128(uint32_t off) { return off ^ ((off >> 3) & 0x70); }

// bf16 truncation split (agent kernel)
__device__ __forceinline__ void split2(float v0, float v1, uint32_t& hi, uint32_t& lo) {
    const uint32_t u0 = __float_as_uint(v0), u1 = __float_as_uint(v1);
    hi = __byte_perm(u0, u1, 0x7632);
    const float l0 = v0 - __uint_as_float(u0 & 0xFFFF0000u);
    const float l1 = v1 - __uint_as_float(u1 & 0xFFFF0000u);
    lo = __byte_perm(__float_as_uint(l0), __float_as_uint(l1), 0x7632);
}
// fp16 pack (edge kernel A)
__device__ __forceinline__ uint32_t pack_h2(float v0, float v1) {
    __half2 h = __floats2half2_rn(v0, v1);
    return *(uint32_t*)&h;
}

#if HAS_TCGEN05
__device__ __forceinline__ uint64_t mk_desc(uint32_t addr) {
    const uint64_t base = (uint64_t(2) << 61) | (uint64_t(1) << 46) | (uint64_t(64) << 32) | (uint64_t(1) << 16);
    return base | ((uint64_t)(addr >> 4) & 0x3FFF);
}
__device__ __forceinline__ void mma_f16_ss(uint32_t d, uint64_t a, uint64_t b, uint32_t idesc, uint32_t en) {
    asm volatile(
        "{\n\t.reg .pred p;\n\tsetp.ne.u32 p, %5, 0;\n\t"
        "tcgen05.mma.cta_group::1.kind::f16 [%0], %1, %2, %3, {%4,%4,%4,%4}, p;\n\t}"
        :: "r"(d), "l"(a), "l"(b), "r"(idesc), "r"(0u), "r"(en) : "memory");
}
#define TC_ALLOC(sa, n)   asm volatile("tcgen05.alloc.cta_group::1.sync.aligned.shared::cta.b32 [%0], %1;" :: "r"(sa), "r"(n) : "memory")
#define TC_RELINQ()       asm volatile("tcgen05.relinquish_alloc_permit.cta_group::1.sync.aligned;")
#define TC_DEALLOC(t, n)  asm volatile("tcgen05.dealloc.cta_group::1.sync.aligned.b32 %0, %1;" :: "r"(t), "r"(n))
#define TC_COMMIT(mb)     asm volatile("tcgen05.commit.cta_group::1.mbarrier::arrive::one.shared::cluster.b64 [%0];" :: "r"(mb) : "memory")
#define TC_FENCE_AFTER()  asm volatile("tcgen05.fence::after_thread_sync;" ::: "memory")
#define TC_FENCE_BEFORE() asm volatile("tcgen05.fence::before_thread_sync;" ::: "memory")
#define TC_WAIT_LD()      asm volatile("tcgen05.wait::ld.sync.aligned;" ::: "memory")
#define FENCE_ASYNC()     asm volatile("fence.proxy.async.shared::cta;" ::: "memory")
#define MBAR_INIT(mb, c)  asm volatile("mbarrier.init.shared.b64 [%0], %1;" :: "r"(mb), "r"(c) : "memory")
#define MBAR_EXPECT_TX(mb, n) asm volatile("mbarrier.arrive.expect_tx.shared.b64 _, [%0], %1;" :: "r"(mb), "r"(n) : "memory")
#define BULK_CP(dst, src, bytes, mbar) \
    asm volatile("cp.async.bulk.shared::cta.global.mbarrier::complete_tx::bytes [%0], [%1], %2, [%3];" \
        :: "r"(dst), "l"(src), "r"(bytes), "r"(mbar) : "memory")

#define MBAR_WAIT(mb, par) do { \
    uint32_t _m = (mb); uint32_t _p = (par); uint32_t _d; \
    asm volatile("{\n\t.reg .pred p;\n\t" \
        "mbarrier.try_wait.parity.acquire.cta.shared::cta.b64 p, [%1], %2;\n\t" \
        "selp.b32 %0, 1, 0, p;\n\t}" : "=r"(_d) : "r"(_m), "r"(_p) : "memory"); \
    if (!_d) { \
        asm volatile("{\n\t.reg .pred P1;\n\t" \
            "WL_%=:\n\t" \
            "mbarrier.try_wait.parity.acquire.cta.shared::cta.b64 P1, [%0], %1, 0x989680;\n\t" \
            "@P1 bra.uni WD_%=;\n\t" \
            "bra.uni WL_%=;\n\t" \
            "WD_%=:\n\t}" :: "r"(_m), "r"(_p) : "memory"); \
    } \
} while (0)

#define TC_LD_X32(r, ta) \
    asm volatile("tcgen05.ld.sync.aligned.32x32b.x32.b32 " \
        "{%0,%1,%2,%3,%4,%5,%6,%7,%8,%9,%10,%11,%12,%13,%14,%15," \
        "%16,%17,%18,%19,%20,%21,%22,%23,%24,%25,%26,%27,%28,%29,%30,%31}, [%32];" \
        : "=r"((r)[0]),"=r"((r)[1]),"=r"((r)[2]),"=r"((r)[3]),"=r"((r)[4]),"=r"((r)[5]),"=r"((r)[6]),"=r"((r)[7]), \
          "=r"((r)[8]),"=r"((r)[9]),"=r"((r)[10]),"=r"((r)[11]),"=r"((r)[12]),"=r"((r)[13]),"=r"((r)[14]),"=r"((r)[15]), \
          "=r"((r)[16]),"=r"((r)[17]),"=r"((r)[18]),"=r"((r)[19]),"=r"((r)[20]),"=r"((r)[21]),"=r"((r)[22]),"=r"((r)[23]), \
          "=r"((r)[24]),"=r"((r)[25]),"=r"((r)[26]),"=r"((r)[27]),"=r"((r)[28]),"=r"((r)[29]),"=r"((r)[30]),"=r"((r)[31]) \
        : "r"(ta))
#endif // HAS_TCGEN05

// idescs: dtype=F32(1<<4); bf16: atype/btype=1; fp16: atype/btype=0
#define IDESC_N128     0x8200490u   // bf16, N=128 (agent)
#define IDESC_N256_F16 0x8400010u   // fp16, N=256 (edge L2)
#define IDESC_N64_F16  0x8100010u   // fp16, N=64  (edge L3)

// ---------------- edge smem layout (88KB -> 2 CTAs/SM) ----------------
#define E_TMEM  0
#define E_MBA   16      // commit-A (after Bh MMAs)
#define E_MBB   24      // commit-B (after all MMAs)
#define E_MBT   32      // B-hi DMA barrier
#define E_MBTL  48      // B-lo DMA barrier
#define E_SSEG  64      // 2 x 128 ints
#define E_BP2   1088
#define E_BP3   2112
#define E_BP1   2368
#define E_WP1   3392    // 1024 f
#define E_A     8192    // 16KB: fp16 A (hi only)
#define E_B     24576   // 64KB: hi 32K + lo 32K (h3T aliases here)
#define EDGE_SMEM 92160

// ---------------- agent smem layout (R9, unchanged) ----------------
#define AG_TMEM  0
#define AG_MBAR0 16
#define AG_MBAR1 24
#define AG_MBT0  32
#define AG_MBT1  40
#define AG_BP2   1088
#define AG_BP1   2368
#define AG_WP1   3392
#define AG_A0    8192
#define AG_A1    40960
#define AG_B0    73728
#define AG_B1    139264
#define AGENT_SMEM 204800

#define NT_EDGE 256
#define NCTA_EDGE 296

// ---------------- merged weight prep + agg zero ----------------
__global__ void prep_kernel(const float* __restrict__ Wp2, const float* __restrict__ Wp3,
                            const float* __restrict__ Wr1, const float* __restrict__ Wr2) {
    int i = blockIdx.x * blockDim.x + threadIdx.x;
    if (i < N_AG * AGG_STRIDE) g_agg[i] = 0.0f;
    if (i < 256 * 256) {
        int n = i >> 8, k = i & 255;
        {   // Wp2 -> fp16 hi+lo SW128 image
            float w = Wp2[k * 256 + n];
            __half h = __float2half_rn(w);
            float r = w - __half2float(h);
            const uint32_t off = (k >> 6) * 32768 + swz128(n * 128 + (k & 63) * 2);
            *(__half*)((char*)g_W2S_hi + off) = h;
            *(__half*)((char*)g_W2S_lo + off) = __float2half_rn(r);
        }
        {   // Wr2 -> bf16 image (agent)
            float w = Wr2[k * 256 + n];
            __nv_bfloat16 h = __float2bfloat16(w);
            float r = w - __bfloat162float(h);
            const uint32_t off = (k >> 6) * 32768 + swz128(n * 128 + (k & 63) * 2);
            *(__nv_bfloat16*)((char*)g_WR2S_hi + off) = h;
            *(__nv_bfloat16*)((char*)g_WR2S_lo + off) = __float2bfloat16(r);
        }
    }
    if (i < 64 * 256) {
        int n = i >> 8, k = i & 255;   // Wp3 [256,64] -> fp16 image
        float w = Wp3[k * 64 + n];
        __half h = __float2half_rn(w);
        float r = w - __half2float(h);
        const uint32_t off = (k >> 6) * 8192 + swz128(n * 128 + (k & 63) * 2);
        *(__half*)((char*)g_W3S_hi + off) = h;
        *(__half*)((char*)g_W3S_lo + off) = __float2half_rn(r);
    }
    if (i < 256 * 64) {
        int n = i >> 6, k = i & 63;    // Wr1 [64,256] bf16 (agent)
        float w = Wr1[k * 256 + n];
        __nv_bfloat16 h = __float2bfloat16(w);
        float r = w - __bfloat162float(h);
        const uint32_t off = swz128(n * 128 + k * 2);
        *(__nv_bfloat16*)((char*)g_WR1S_hi + off) = h;
        *(__nv_bfloat16*)((char*)g_WR1S_lo + off) = __float2bfloat16(r);
    }
}

// barrier term + segmented-scan epilogue (h3T rows 0..63 already written)
__device__ __forceinline__ void do_epilogue(float* h3T, const int* ss, float px, float py, int tid) {
    if (tid < 128) {
        const float d = sqrtf(px * px + py * py);
        const float s = -1.0f / (d * (d - 0.18f));
        h3T[64 * 132 + tid] = px * s;
        h3T[65 * 132 + tid] = py * s;
    }
    __syncthreads();
    const int sc = (tid < 66) ? 0 : ((tid >= 128 && tid < 194) ? 1 : -1);
    if (sc >= 0) {
        const int col = (sc == 0) ? tid : (tid - 128);
        const int eb = sc * 64;
        const float* colp = h3T + col * 132 + eb;
        int cur = ss[eb];
        float run = 0.0f;
        #pragma unroll 4
        for (int e = 0; e < 64; e++) {
            const int sg = ss[eb + e];
            if (sg != cur) { atomicAdd(&g_agg[cur * 66 + col], run); run = 0.0f; cur = sg; }
            run += colp[e];
        }
        atomicAdd(&g_agg[cur * 66 + col], run);
    }
    __syncthreads();
}

// ---------------- edge kernel: fp16 A + fp16 hi/lo B, 8 MMAs/chunk ----------------
__global__ void __launch_bounds__(NT_EDGE, 2) edge_kernel(
    const float* __restrict__ ef, const int* __restrict__ seg,
    const float* __restrict__ Wp1, const float* __restrict__ bp1,
    const float* __restrict__ bp2, const float* __restrict__ bp3,
    const float* __restrict__ Wp2g, const float* __restrict__ Wp3g)
{
    extern __shared__ char sm[];
    const uint32_t smb = smem_u32(sm);
    const int tid = threadIdx.x;
    const int wid = tid >> 5;
    const int edge = tid & 127;
    const int half = tid >> 7;

    int*   sbuf = (int*)(sm + E_SSEG);
    float* bp2s = (float*)(sm + E_BP2);
    float* bp3s = (float*)(sm + E_BP3);
    float* bp1s = (float*)(sm + E_BP1);
    float* wp1s = (float*)(sm + E_WP1);
    float* h3T  = (float*)(sm + E_B);       // aliases B region (idle during epilogue)

#if HAS_TCGEN05
    if (wid == 0) { TC_ALLOC(smb + E_TMEM, 256); TC_RELINQ(); }
    if (tid == 0) {
        MBAR_INIT(smb + E_MBA, 1);
        MBAR_INIT(smb + E_MBB, 1);
        MBAR_INIT(smb + E_MBT, 1);
        MBAR_INIT(smb + E_MBTL, 1);
    }
#endif

    wp1s[tid] = Wp1[tid];             wp1s[tid + 256] = Wp1[tid + 256];
    wp1s[tid + 512] = Wp1[tid + 512]; wp1s[tid + 768] = Wp1[tid + 768];
    bp1s[tid] = bp1[tid];
    bp2s[tid] = bp2[tid];
    if (tid < 64) bp3s[tid] = bp3[tid];
    __syncthreads();

#if HAS_TCGEN05
    uint32_t tmem;
    asm volatile("ld.shared.b32 %0, [%1];" : "=r"(tmem) : "r"(smb + E_TMEM));
    const uint32_t tD2 = tmem;        // 256 cols
    const uint32_t tD3 = tmem;        // cols 0-63, read before clobber
    const uint32_t warp_off = (uint32_t)(wid & 3) << 21;
    int parA = 0, parB = 0, pend = 0;
    int pt = 0, ptl = 0;

    const char* w2h = (const char*)g_W2S_hi;
    const char* w2l = (const char*)g_W2S_lo;
    const char* w3h = (const char*)g_W3S_hi;
    const char* w3l = (const char*)g_W3S_lo;

    float4 xcur = make_float4(0.f, 0.f, 0.f, 0.f), xprev;
    int cnt = 0;

    for (int tile = blockIdx.x; tile < NTILES; tile += gridDim.x, cnt++) {
        const int e0 = tile * 128;
        const int sb = cnt & 1;
        xprev = xcur;
        xcur = ((const float4*)ef)[e0 + edge];
        if (tid < 128) sbuf[sb * 128 + tid] = seg[e0 + tid];

        // drain previous tile (both commits)
        if (pend) {
            MBAR_WAIT(smb + E_MBA, parA); parA ^= 1;
            MBAR_WAIT(smb + E_MBB, parB); parB ^= 1;
            pend = 0;
        }
        TC_FENCE_AFTER();

        // -------- epilogue of PREVIOUS tile --------
        if (cnt > 0) {
            uint32_t r0[32];
            TC_LD_X32(r0, tD3 + half * 32 + warp_off);
            TC_WAIT_LD();
            TC_FENCE_BEFORE();
            #pragma unroll
            for (int c = 0; c < 32; c++)
                h3T[(half * 32 + c) * 132 + edge] = __uint_as_float(r0[c]) + bp3s[half * 32 + c];
            do_epilogue(h3T, sbuf + (sb ^ 1) * 128, xprev.x, xprev.y, tid);
        }

        // ================= layer 2: K=256 in 4 chunks of 64 =================
        for (int kc = 0; kc < 4; kc++) {
            if (kc > 0) {
                // commit-A of kc-1: Bh free -> early Bh DMA
                MBAR_WAIT(smb + E_MBA, parA); parA ^= 1;
                if (tid == 0) {
                    MBAR_EXPECT_TX(smb + E_MBT, 32768);
                    BULK_CP(smb + E_B, w2h + kc * 32768, 32768, smb + E_MBT);
                }
                // commit-B of kc-1: Bl + A free
                MBAR_WAIT(smb + E_MBB, parB); parB ^= 1;
                if (tid == 0) {
                    MBAR_EXPECT_TX(smb + E_MBTL, 32768);
                    BULK_CP(smb + E_B + 32768, w2l + kc * 32768, 32768, smb + E_MBTL);
                }
            } else {
                if (tid == 0) {
                    MBAR_EXPECT_TX(smb + E_MBT, 32768);
                    BULK_CP(smb + E_B, w2h, 32768, smb + E_MBT);
                    MBAR_EXPECT_TX(smb + E_MBTL, 32768);
                    BULK_CP(smb + E_B + 32768, w2l, 32768, smb + E_MBTL);
                }
            }

            // layer-1 on the fly: 32 of the 64 chunk cols per thread, fp16 A (hi only)
            #pragma unroll
            for (int g = 0; g < 4; g++) {
                const int gg = half * 4 + g;
                uint32_t hi4[4];
                #pragma unroll
                for (int q = 0; q < 4; q++) {
                    const int c = kc * 64 + gg * 8 + q * 2;
                    float v0 = fmaf(xcur.x, wp1s[c],       fmaf(xcur.y, wp1s[256 + c],
                               fmaf(xcur.z, wp1s[512 + c], fmaf(xcur.w, wp1s[768 + c], bp1s[c]))));
                    float v1 = fmaf(xcur.x, wp1s[c + 1],       fmaf(xcur.y, wp1s[256 + c + 1],
                               fmaf(xcur.z, wp1s[512 + c + 1], fmaf(xcur.w, wp1s[768 + c + 1], bp1s[c + 1]))));
                    hi4[q] = pack_h2(fmaxf(v0, 0.0f), fmaxf(v1, 0.0f));
                }
                const uint32_t so = swz128(edge * 128 + gg * 16);
                *(uint4*)(sm + E_A + so) = make_uint4(hi4[0], hi4[1], hi4[2], hi4[3]);
            }
            FENCE_ASYNC();
            __syncthreads();

            if (tid == 0) {
                const uint64_t dA  = mk_desc(smb + E_A);
                const uint64_t dBh = mk_desc(smb + E_B);
                const uint64_t dBl = dBh + 2048;   // +32KB
                MBAR_WAIT(smb + E_MBT, pt); pt ^= 1;
                #pragma unroll
                for (int s = 0; s < 4; s++)
                    mma_f16_ss(tD2, dA + s * 2, dBh + s * 2, IDESC_N256_F16, !(kc == 0 && s == 0));
                TC_COMMIT(smb + E_MBA);
                MBAR_WAIT(smb + E_MBTL, ptl); ptl ^= 1;
                #pragma unroll
                for (int s = 0; s < 4; s++)
                    mma_f16_ss(tD2, dA + s * 2, dBl + s * 2, IDESC_N256_F16, 1);
                TC_COMMIT(smb + E_MBB);
            }
            pend = 1;
        }

        // ================= layer 3: 4 slices, D3 = cols 0-63 =================
        for (int i = 0; i < 4; i++) {
            MBAR_WAIT(smb + E_MBA, parA); parA ^= 1;
            MBAR_WAIT(smb + E_MBB, parB); parB ^= 1;
            pend = 0;
            TC_FENCE_AFTER();

            if (tid == 0) {
                MBAR_EXPECT_TX(smb + E_MBT, 8192);
                BULK_CP(smb + E_B, w3h + i * 8192, 8192, smb + E_MBT);
                MBAR_EXPECT_TX(smb + E_MBTL, 8192);
                BULK_CP(smb + E_B + 8192, w3l + i * 8192, 8192, smb + E_MBTL);
            }

            uint32_t r0[32];
            TC_LD_X32(r0, tD2 + i * 64 + half * 32 + warp_off);
            TC_WAIT_LD();

            #pragma unroll
            for (int g = 0; g < 4; g++) {
                const int gg = half * 4 + g;
                uint32_t hi4[4];
                #pragma unroll
                for (int q = 0; q < 4; q++) {
                    const int j = g * 8 + q * 2;
                    const int c = i * 64 + half * 32 + j;
                    float v0 = fmaxf(__uint_as_float(r0[j])     + bp2s[c],     0.0f);
                    float v1 = fmaxf(__uint_as_float(r0[j + 1]) + bp2s[c + 1], 0.0f);
                    hi4[q] = pack_h2(v0, v1);
                }
                const uint32_t so = swz128(edge * 128 + gg * 16);
                *(uint4*)(sm + E_A + so) = make_uint4(hi4[0], hi4[1], hi4[2], hi4[3]);
            }
            FENCE_ASYNC();
            TC_FENCE_BEFORE();
            __syncthreads();

            if (tid == 0) {
                TC_FENCE_AFTER();
                const uint64_t dA  = mk_desc(smb + E_A);
                const uint64_t dBh = mk_desc(smb + E_B);
                const uint64_t dBl = dBh + 512;    // +8KB
                MBAR_WAIT(smb + E_MBT, pt); pt ^= 1;
                #pragma unroll
                for (int s = 0; s < 4; s++)
                    mma_f16_ss(tD3, dA + s * 2, dBh + s * 2, IDESC_N64_F16, !(i == 0 && s == 0));
                TC_COMMIT(smb + E_MBA);
                MBAR_WAIT(smb + E_MBTL, ptl); ptl ^= 1;
                #pragma unroll
                for (int s = 0; s < 4; s++)
                    mma_f16_ss(tD3, dA + s * 2, dBl + s * 2, IDESC_N64_F16, 1);
                TC_COMMIT(smb + E_MBB);
            }
            pend = 1;
        }
    }

    // -------- final drain + epilogue of the last tile --------
    if (pend) {
        MBAR_WAIT(smb + E_MBA, parA); parA ^= 1;
        MBAR_WAIT(smb + E_MBB, parB); parB ^= 1;
        pend = 0;
    }
    if (cnt > 0) {
        TC_FENCE_AFTER();
        uint32_t r0[32];
        TC_LD_X32(r0, tD3 + half * 32 + warp_off);
        TC_WAIT_LD();
        TC_FENCE_BEFORE();
        #pragma unroll
        for (int c = 0; c < 32; c++)
            h3T[(half * 32 + c) * 132 + edge] = __uint_as_float(r0[c]) + bp3s[half * 32 + c];
        do_epilogue(h3T, sbuf + ((cnt - 1) & 1) * 128, xcur.x, xcur.y, tid);
    }
    __syncthreads();
    if (wid == 0) TC_DEALLOC(tmem, 256);
#else
    // ---------- correct scalar fallback (non-'a' targets only) ----------
    for (int tile = blockIdx.x; tile < NTILES; tile += gridDim.x) {
        const int e0 = tile * 128;
        const float4 x = ((const float4*)ef)[e0 + edge];
        if (tid < 128) sbuf[tid] = seg[e0 + tid];
        __syncthreads();
        if (tid < 128) {
            float h1v[256];
            for (int k = 0; k < 256; k++) {
                float v = fmaf(x.x, wp1s[k],       fmaf(x.y, wp1s[256 + k],
                          fmaf(x.z, wp1s[512 + k], fmaf(x.w, wp1s[768 + k], bp1s[k]))));
                h1v[k] = fmaxf(v, 0.0f);
            }
            float h3a[64];
            for (int n = 0; n < 64; n++) h3a[n] = bp3s[n];
            for (int j = 0; j < 256; j++) {
                float s = bp2s[j];
                for (int k = 0; k < 256; k++)
                    s = fmaf(h1v[k], Wp2g[k * 256 + j], s);
                s = fmaxf(s, 0.0f);
                for (int n = 0; n < 64; n++)
                    h3a[n] = fmaf(s, Wp3g[j * 64 + n], h3a[n]);
            }
            for (int c = 0; c < 64; c++)
                h3T[c * 132 + tid] = h3a[c];
        }
        __syncthreads();
        do_epilogue(h3T, sbuf, x.x, x.y, tid);
        __syncthreads();
    }
#endif
}

// ---------------- agent kernel: tcgen05, 128 agents/CTA, one wave (R9 verbatim, bf16) ----------------
__global__ void __launch_bounds__(256, 1) agent_kernel(
    const float* __restrict__ Wr1, const float* __restrict__ br1,
    const float* __restrict__ Wr2, const float* __restrict__ br2,
    const float* __restrict__ Wr3, const float* __restrict__ br3,
    float* __restrict__ out)
{
    extern __shared__ char sm[];
    const uint32_t smb = smem_u32(sm);
    const int tid = threadIdx.x;
    const int wid = tid >> 5;
    const int edge = tid & 127;
    const int half = tid >> 7;
    const int a0 = blockIdx.x * 128;

    float* br1s = (float*)(sm + AG_BP1);
    float* br2s = (float*)(sm + AG_BP2);
    float* w3s  = (float*)(sm + AG_WP1);

    br1s[tid] = br1[tid];
    br2s[tid] = br2[tid];
    w3s[tid] = Wr3[tid];
    w3s[tid + 256] = Wr3[tid + 256];

#if HAS_TCGEN05
    if (wid == 0) { TC_ALLOC(smb + AG_TMEM, 512); TC_RELINQ(); }
    if (tid == 0) {
        MBAR_INIT(smb + AG_MBAR0, 1); MBAR_INIT(smb + AG_MBAR1, 1);
        MBAR_INIT(smb + AG_MBT0, 1);  MBAR_INIT(smb + AG_MBT1, 1);
    }
    __syncthreads();

    uint32_t tmem;
    asm volatile("ld.shared.b32 %0, [%1];" : "=r"(tmem) : "r"(smb + AG_TMEM));
    const uint32_t tD1 = tmem;
    const uint32_t tD2 = tmem + 256;
    const uint32_t warp_off = (uint32_t)(wid & 3) << 21;
    int par0 = 0, par1 = 0, pend0 = 0, pend1 = 0;
    int pt0 = 0, pt1 = 0;

#define WAIT_BUF0() do { if (pend0) { MBAR_WAIT(smb + AG_MBAR0, par0); par0 ^= 1; pend0 = 0; } } while (0)
#define WAIT_BUF1() do { if (pend1) { MBAR_WAIT(smb + AG_MBAR1, par1); par1 ^= 1; pend1 = 0; } } while (0)

    if (tid == 0) {
        MBAR_EXPECT_TX(smb + AG_MBT0, 65536);
        BULK_CP(smb + AG_B0,         (const char*)g_WR1S_hi, 32768, smb + AG_MBT0);
        BULK_CP(smb + AG_B0 + 32768, (const char*)g_WR1S_lo, 32768, smb + AG_MBT0);
    }
    {
        char* A = sm + AG_A0;
        const float* aggrow = g_agg + (size_t)(a0 + edge) * 66 + half * 32;
        #pragma unroll
        for (int g = 0; g < 4; g++) {
            const int gg = half * 4 + g;
            uint32_t hi4[4], lo4[4];
            #pragma unroll
            for (int q = 0; q < 4; q++) {
                const int j = g * 8 + q * 2;
                const float2 v = *(const float2*)&aggrow[j];
                split2(v.x, v.y, hi4[q], lo4[q]);
            }
            const uint32_t so = swz128(edge * 128 + gg * 16);
            *(uint4*)(A + so)         = make_uint4(hi4[0], hi4[1], hi4[2], hi4[3]);
            *(uint4*)(A + 16384 + so) = make_uint4(lo4[0], lo4[1], lo4[2], lo4[3]);
        }
    }
    FENCE_ASYNC();
    __syncthreads();

    if (tid == 0) {
        MBAR_WAIT(smb + AG_MBT0, pt0); pt0 ^= 1;
        const uint64_t dAh = mk_desc(smb + AG_A0);
        const uint64_t dAl = dAh + 1024;
        const uint64_t dBh = mk_desc(smb + AG_B0);
        const uint64_t dBl = dBh + 2048;
        #pragma unroll
        for (int s = 0; s < 4; s++) {
            #pragma unroll
            for (int h = 0; h < 2; h++) {
                const uint32_t d = tD1 + h * 128;
                const uint64_t bo = (uint64_t)h * 1024 + s * 2;
                mma_f16_ss(d, dAh + s * 2, dBh + bo, IDESC_N128, !(s == 0));
                mma_f16_ss(d, dAh + s * 2, dBl + bo, IDESC_N128, 1);
                mma_f16_ss(d, dAl + s * 2, dBh + bo, IDESC_N128, 1);
            }
        }
        TC_COMMIT(smb + AG_MBAR0);
    }
    pend0 = 1;
    WAIT_BUF0();
    TC_FENCE_AFTER();

    for (int kc = 0; kc < 4; kc++) {
        const int buf = (kc & 1) ^ 1;
        if (buf) WAIT_BUF1(); else WAIT_BUF0();

        char* A = sm + (buf ? AG_A1 : AG_A0);
        const uint32_t Bsm = smb + (buf ? AG_B1 : AG_B0);
        const uint32_t mbt = smb + (buf ? AG_MBT1 : AG_MBT0);

        if (tid == 0) {
            MBAR_EXPECT_TX(mbt, 65536);
            BULK_CP(Bsm,         (const char*)g_WR2S_hi + kc * 32768, 32768, mbt);
            BULK_CP(Bsm + 32768, (const char*)g_WR2S_lo + kc * 32768, 32768, mbt);
        }

        uint32_t r0[32];
        TC_LD_X32(r0, tD1 + kc * 64 + half * 32 + warp_off);
        TC_WAIT_LD();

        #pragma unroll
        for (int g = 0; g < 4; g++) {
            const int gg = half * 4 + g;
            uint32_t hi4[4], lo4[4];
            #pragma unroll
            for (int q = 0; q < 4; q++) {
                const int j = g * 8 + q * 2;
                const int c = kc * 64 + half * 32 + j;
                float v0 = fmaxf(__uint_as_float(r0[j])     + br1s[c],     0.0f);
                float v1 = fmaxf(__uint_as_float(r0[j + 1]) + br1s[c + 1], 0.0f);
                split2(v0, v1, hi4[q], lo4[q]);
            }
            const uint32_t so = swz128(edge * 128 + gg * 16);
            *(uint4*)(A + so)         = make_uint4(hi4[0], hi4[1], hi4[2], hi4[3]);
            *(uint4*)(A + 16384 + so) = make_uint4(lo4[0], lo4[1], lo4[2], lo4[3]);
        }
        FENCE_ASYNC();
        TC_FENCE_BEFORE();
        __syncthreads();

        if (tid == 0) {
            TC_FENCE_AFTER();
            if (buf) { MBAR_WAIT(mbt, pt1); pt1 ^= 1; }
            else     { MBAR_WAIT(mbt, pt0); pt0 ^= 1; }
            const uint64_t dAh = mk_desc(smb + (uint32_t)(A - sm));
            const uint64_t dAl = dAh + 1024;
            const uint64_t dBh = mk_desc(Bsm);
            const uint64_t dBl = dBh + 2048;
            #pragma unroll
            for (int s = 0; s < 4; s++) {
                #pragma unroll
                for (int h = 0; h < 2; h++) {
                    const uint32_t d = tD2 + h * 128;
                    const uint64_t bo = (uint64_t)h * 1024 + s * 2;
                    mma_f16_ss(d, dAh + s * 2, dBh + bo, IDESC_N128, !(kc == 0 && s == 0));
                    mma_f16_ss(d, dAh + s * 2, dBl + bo, IDESC_N128, 1);
                    mma_f16_ss(d, dAl + s * 2, dBh + bo, IDESC_N128, 1);
                }
            }
            TC_COMMIT(smb + (buf ? AG_MBAR1 : AG_MBAR0));
        }
        if (buf) pend1 = 1; else pend0 = 1;
    }

    WAIT_BUF0();
    WAIT_BUF1();
    TC_FENCE_AFTER();

    if (tid < 128) {
        float s0 = br3[0] + g_agg[(size_t)(a0 + edge) * 66 + 64];
        float s1 = br3[1] + g_agg[(size_t)(a0 + edge) * 66 + 65];
        #pragma unroll
        for (int b = 0; b < 8; b++) {
            uint32_t r0[32];
            TC_LD_X32(r0, tD2 + b * 32 + warp_off);
            TC_WAIT_LD();
            #pragma unroll
            for (int j = 0; j < 32; j++) {
                const int c = b * 32 + j;
                const float v = fmaxf(__uint_as_float(r0[j]) + br2s[c], 0.0f);
                s0 = fmaf(v, w3s[c * 2],     s0);
                s1 = fmaf(v, w3s[c * 2 + 1], s1);
            }
        }
        TC_FENCE_BEFORE();
        out[(a0 + edge) * 2]     = s0;
        out[(a0 + edge) * 2 + 1] = s1;
    }
    __syncthreads();
    if (wid == 0) TC_DEALLOC(tmem, 512);
#undef WAIT_BUF0
#undef WAIT_BUF1
#else
    __syncthreads();
    if (tid < 128) {
        const int a = a0 + edge;
        float r1v[256];
        for (int n = 0; n < 256; n++) {
            float s = br1s[n];
            for (int k = 0; k < 64; k++)
                s = fmaf(g_agg[(size_t)a * 66 + k], Wr1[k * 256 + n], s);
            r1v[n] = fmaxf(s, 0.0f);
        }
        float s0 = br3[0] + g_agg[(size_t)a * 66 + 64];
        float s1 = br3[1] + g_agg[(size_t)a * 66 + 65];
        for (int n = 0; n < 256; n++) {
            float s = br2s[n];
            for (int k = 0; k < 256; k++)
                s = fmaf(r1v[k], Wr2[k * 256 + n], s);
            s = fmaxf(s, 0.0f);
            s0 = fmaf(s, w3s[n * 2],     s0);
            s1 = fmaf(s, w3s[n * 2 + 1], s1);
        }
        out[a * 2]     = s0;
        out[a * 2 + 1] = s1;
    }
#endif
}

// ---------------- launch ----------------
extern "C" void kernel_launch(void* const* d_in, const int* in_sizes, int n_in,
                              void* d_out, int out_size) {
    const float* ef  = (const float*)d_in[0];
    const int*   seg = (const int*)  d_in[1];
    const float* Wp1 = (const float*)d_in[2];
    const float* bp1 = (const float*)d_in[3];
    const float* Wp2 = (const float*)d_in[4];
    const float* bp2 = (const float*)d_in[5];
    const float* Wp3 = (const float*)d_in[6];
    const float* bp3 = (const float*)d_in[7];
    const float* Wr1 = (const float*)d_in[8];
    const float* br1 = (const float*)d_in[9];
    const float* Wr2 = (const float*)d_in[10];
    const float* br2 = (const float*)d_in[11];
    const float* Wr3 = (const float*)d_in[12];
    const float* br3 = (const float*)d_in[13];
    float* out = (float*)d_out;

    cudaFuncSetAttribute(edge_kernel,  cudaFuncAttributeMaxDynamicSharedMemorySize, EDGE_SMEM);
    cudaFuncSetAttribute(agent_kernel, cudaFuncAttributeMaxDynamicSharedMemorySize, AGENT_SMEM);

    prep_kernel<<<(N_AG * AGG_STRIDE + 255) / 256, 256>>>(Wp2, Wp3, Wr1, Wr2);
    edge_kernel<<<NCTA_EDGE, NT_EDGE, EDGE_SMEM>>>(ef, seg, Wp1, bp1, bp2, bp3, Wp2, Wp3);
    agent_kernel<<<N_AG / 128, 256, AGENT_SMEM>>>(Wr1, br1, Wr2, br2, Wr3, br3, out);
}